// round 15
// baseline (speedup 1.0000x reference)
#include <cuda_runtime.h>

#define NN   8192
#define NB   32                  // time buckets
#define BSZ  512                 // padded bucket capacity
#define GRID 296                 // 148 SMs * 2 CTAs -> all resident (barrier-safe)
#define T    512
#define PBLK 32                  // prep blocks (== NB)
#define PE   256                 // elements per prep block

// ---------------- device scratch (no allocation) ----------------
__device__ int    g_histT[NB][PBLK];
__device__ int    g_histA[NB][PBLK];
__device__ float  g_regp[PBLK];
__device__ int    g_bstart[NB + 1];
__device__ int    g_Mg;
__device__ float  g_ts[NN], g_ps[NN];     // time-bucket-sorted (stable)
__device__ float4 g_row4[NN];             // (t, 1+p, bits(b), bits(bstart[b+1]))
__device__ float  g_sp[NB][BSZ];          // p-sorted per bucket (+INF pads)
__device__ float2 g_S[NB][BSZ + 1];       // exclusive prefix (Σp, Σp²)
__device__ float  g_rankp[GRID];
__device__ int    g_cntp[GRID];
__device__ volatile unsigned g_bar0, g_bar1, g_bar2;
__device__ unsigned g_ticket;

union SmemU {
    struct { int wh[8][NB]; int wha[8][NB]; float red[T];
             int bs[NB + 1], bsA[NB + 1], my[NB], myA[NB]; } s1;       // ~4.9 KB
    struct { unsigned long long key[BSZ]; float2 sa[BSZ]; float2 sb[BSZ]; } s2; // 12 KB
    struct { float p[4][BSZ]; float2 S[4][BSZ + 1]; } s3;              // 24.6 KB
    struct { double fr[T]; double fc[T]; double fg[T]; } s4;           // 12 KB
};

__global__ void __launch_bounds__(T, 2)
svm_all(const float* __restrict__ pred,
        const float* __restrict__ target,
        float* __restrict__ out)
{
    __shared__ SmemU U;
    __shared__ double sr[T];
    __shared__ int    sc2[T];
    __shared__ int    sbs[NB + 1];
    __shared__ bool   slast;

    const int tid  = threadIdx.x;
    const int bid  = blockIdx.x;
    const int w    = tid >> 5;
    const int lane = tid & 31;
    const unsigned lt = (1u << lane) - 1u;

    if (bid < PBLK) {
        // ================= Stage 1: bucketize + regression =================
        ((int*)U.s1.wh)[tid] = 0;            // zeroes wh+wha (2*8*32 == 512)
        __syncthreads();

        float tval = 0.f, pval = 0.f;
        int   b = 0, lr = 0, lra = 0;
        bool  act = false;
        if (tid < PE) {                      // warps 0..7 fully active
            const int i = bid * PE + tid;
            const float2 te = ((const float2*)target)[i];
            pval = pred[i];
            tval = te.x;
            int bb = (int)(tval * (NB / 100.0f));   // monotone bucketing
            b = bb < 0 ? 0 : (bb > NB - 1 ? NB - 1 : bb);
            act = (te.y != 0.f);
            float d = pval - tval;
            if (!act) d = fmaxf(d, 0.f);
            U.s1.red[tid] = d * d;

            const unsigned mm = __match_any_sync(0xffffffffu, b);
            lr = __popc(mm & lt);
            if (lane == __ffs(mm) - 1) U.s1.wh[w][b] = __popc(mm);
            const unsigned am = __ballot_sync(0xffffffffu, act);
            const unsigned mma = mm & am;
            lra = __popc(mma & lt);
            if (act && lane == __ffs(mma) - 1) U.s1.wha[w][b] = __popc(mma);
        } else {
            U.s1.red[tid] = 0.f;
        }
        __syncthreads();

        if (tid < NB) {
            int h = 0, ha = 0;
            #pragma unroll
            for (int q = 0; q < 8; ++q) { h += U.s1.wh[q][tid]; ha += U.s1.wha[q][tid]; }
            g_histT[tid][bid] = h;
            g_histA[tid][bid] = ha;
        }
        #pragma unroll
        for (int s = T / 2; s > 0; s >>= 1) {
            __syncthreads();
            if (tid < s) U.s1.red[tid] += U.s1.red[tid + s];
        }
        __syncthreads();
        if (tid == 0) g_regp[bid] = U.s1.red[0];

        __threadfence();
        __syncthreads();
        if (tid == 0) {
            atomicAdd((unsigned*)&g_bar0, 1u);
            while (g_bar0 < PBLK) { __nanosleep(32); }
        }
        __syncthreads();
        __threadfence();

        // bucket starts (warp 0 shfl scan) + this block's offsets
        if (tid < NB) {
            int tot = 0, my = 0, tota = 0, mya = 0;
            #pragma unroll 8
            for (int blk = 0; blk < PBLK; ++blk) {
                const int v = g_histT[tid][blk], va = g_histA[tid][blk];
                tot += v; tota += va;
                if (blk < bid) { my += v; mya += va; }
            }
            int sc = tot, sca = tota;
            #pragma unroll
            for (int off = 1; off < 32; off <<= 1) {
                const int v0 = __shfl_up_sync(0xffffffffu, sc, off);
                const int v1 = __shfl_up_sync(0xffffffffu, sca, off);
                if (lane >= off) { sc += v0; sca += v1; }
            }
            U.s1.bs[tid + 1] = sc; U.s1.bsA[tid + 1] = sca;
            if (tid == 0) { U.s1.bs[0] = 0; U.s1.bsA[0] = 0; }
            U.s1.my[tid] = my; U.s1.myA[tid] = mya;
            if (bid == 0) {
                g_bstart[tid + 1] = sc;
                if (tid == 0) g_bstart[0] = 0;
                if (tid == NB - 1) g_Mg = sca;
            }
        }
        __syncthreads();

        // stable scatter
        if (tid < PE) {
            int cw = 0, cwa = 0;
            for (int w2 = 0; w2 < w; ++w2) { cw += U.s1.wh[w2][b]; cwa += U.s1.wha[w2][b]; }
            const int pos = U.s1.bs[b] + U.s1.my[b] + cw + lr;
            g_ts[pos] = tval;
            g_ps[pos] = pval;
            if (act) {
                const int apos = U.s1.bsA[b] + U.s1.myA[b] + cwa + lra;
                g_row4[apos] = make_float4(tval, 1.0f + pval,
                                           __int_as_float(b),
                                           __int_as_float(U.s1.bs[b + 1]));
            }
        }
        // keep own bucket extent before the union is repurposed
        const int start = U.s1.bs[bid];
        const int cntb  = U.s1.bs[bid + 1] - start;

        __threadfence();
        __syncthreads();
        if (tid == 0) {
            atomicAdd((unsigned*)&g_bar1, 1u);
            while (g_bar1 < PBLK) { __nanosleep(32); }
        }
        __syncthreads();
        __threadfence();

        // ================= Stage 2: sort own bucket by p + prefix sums =================
        {
            unsigned long long key = 0xFFFFFFFFFFFFFFFFull;    // pads sort last
            if (tid < cntb) {
                unsigned u = __float_as_uint(g_ps[start + tid]);
                u = (u & 0x80000000u) ? ~u : (u | 0x80000000u);
                key = ((unsigned long long)u << 32) | (unsigned)tid;
            }
            U.s2.key[tid] = key;
        }
        __syncthreads();
        for (int k2 = 2; k2 <= BSZ; k2 <<= 1) {
            for (int j = k2 >> 1; j > 0; j >>= 1) {
                const int ixj = tid ^ j;
                if (ixj > tid) {
                    const bool up = ((tid & k2) == 0);
                    const unsigned long long a = U.s2.key[tid], c = U.s2.key[ixj];
                    if ((a > c) == up) { U.s2.key[tid] = c; U.s2.key[ixj] = a; }
                }
                __syncthreads();
            }
        }
        {
            const unsigned u  = (unsigned)(U.s2.key[tid] >> 32);
            const unsigned pb = (u & 0x80000000u) ? (u ^ 0x80000000u) : ~u;
            const float pv = (tid < cntb) ? __uint_as_float(pb) : 0.f;
            U.s2.sa[tid] = make_float2(pv, pv * pv);
            g_sp[bid][tid] = (tid < cntb) ? __uint_as_float(pb)
                                          : __uint_as_float(0x7f800000u);  // +INF
        }
        __syncthreads();
        {
            float2* pin = U.s2.sa; float2* pout = U.s2.sb;
            #pragma unroll
            for (int off = 1; off < BSZ; off <<= 1) {
                float2 v = pin[tid];
                if (tid >= off) { const float2 q = pin[tid - off]; v.x += q.x; v.y += q.y; }
                pout[tid] = v;
                __syncthreads();
                float2* tmp = pin; pin = pout; pout = tmp;
            }
            g_S[bid][tid + 1] = pin[tid];     // inclusive -> exclusive via +1 shift
            if (tid == 0) g_S[bid][0] = make_float2(0.f, 0.f);
        }
        __threadfence();
        __syncthreads();
        if (tid == 0) atomicAdd((unsigned*)&g_bar2, 1u);
    }

    // ================= all blocks wait for tables =================
    if (tid == 0) { while (g_bar2 < PBLK) { __nanosleep(64); } }
    __syncthreads();
    __threadfence();

    // ================= Stage 3: analytic rank =================
    const int o     = bid & 7;            // octant: buckets 4o..4o+3
    const int chunk = bid >> 3;           // row chunk
    #pragma unroll
    for (int q = 0; q < 4; ++q) {
        const int bb = 4 * o + q;
        U.s3.p[q][tid] = g_sp[bb][tid];
        U.s3.S[q][tid] = g_S[bb][tid];
        if (tid == 0) U.s3.S[q][BSZ] = g_S[bb][BSZ];
    }
    if (tid <= NB) sbs[tid] = g_bstart[tid];
    __syncthreads();

    const int M = g_Mg;
    float acc = 0.f;
    int   cnt = 0;

    // Phase A: full-bucket contributions via prefix-sum expansion
    {
        const int row = chunk * T + tid;
        if (row < M) {
            const float4 f = g_row4[row];
            const float c  = f.y;
            const int   bi = __float_as_int(f.z);
            const float c2 = c * c;
            #pragma unroll
            for (int q = 0; q < 4; ++q) {
                int k = 0;
                #pragma unroll
                for (int s = 256; s > 0; s >>= 1)
                    if (U.s3.p[q][k + s - 1] < c) k += s;    // INF pads: false
                if (4 * o + q > bi) {
                    const float2 S = U.s3.S[q][k];
                    acc += fmaf((float)k, c2, fmaf(-2.f * c, S.x, S.y));
                }
            }
        }
    }

    // Phase B: own-bucket boundary, one warp per row
    for (int rw = bid * (T / 32) + w; rw < M; rw += GRID * (T / 32)) {
        const float4 f = g_row4[rw];
        const float ti = f.x, c = f.y;
        const int bi = __float_as_int(f.z);
        const int sb = __float_as_int(f.w);       // bstart[bi+1]
        const int b0 = sbs[bi];
        if (lane == 0) cnt += NN - sb;            // analytic suffix count
        for (int k = b0 + lane; k < sb; k += 32) {
            const float tj = g_ts[k];
            const float pj = g_ps[k];
            if (tj > ti) {
                const float h = fmaxf(c - pj, 0.f);
                acc = fmaf(h, h, acc);
                cnt++;
            }
        }
    }

    // block reduction (double, deterministic)
    sr[tid]  = (double)acc;
    sc2[tid] = cnt;
    __syncthreads();
    #pragma unroll
    for (int s = T / 2; s > 0; s >>= 1) {
        if (tid < s) { sr[tid] += sr[tid + s]; sc2[tid] += sc2[tid + s]; }
        __syncthreads();
    }

    if (tid == 0) {
        g_rankp[bid] = (float)sr[0];
        g_cntp[bid]  = sc2[0];
        __threadfence();
        slast = (atomicAdd(&g_ticket, 1u) == GRID - 1);
    }
    __syncthreads();

    if (slast) {
        __threadfence();
        double r = 0.0, c = 0.0, g = 0.0;
        if (tid < GRID) { r = (double)g_rankp[tid]; c = (double)g_cntp[tid]; }
        if (tid < PBLK) { g = (double)g_regp[tid]; }
        U.s4.fr[tid] = r; U.s4.fc[tid] = c; U.s4.fg[tid] = g;
        __syncthreads();
        #pragma unroll
        for (int s = T / 2; s > 0; s >>= 1) {
            if (tid < s) {
                U.s4.fr[tid] += U.s4.fr[tid + s];
                U.s4.fc[tid] += U.s4.fc[tid + s];
                U.s4.fg[tid] += U.s4.fg[tid + s];
            }
            __syncthreads();
        }
        if (tid == 0) {
            double cc = U.s4.fc[0];
            if (cc < 1.0) cc = 1.0;
            const double R = 0.5;
            out[0] = (float)(R * (U.s4.fr[0] / cc)
                           + (1.0 - R) * (U.s4.fg[0] / (double)NN));
            g_ticket = 0;          // reset everything for next graph replay
            g_bar0 = 0;
            g_bar1 = 0;
            g_bar2 = 0;
        }
    }
}

extern "C" void kernel_launch(void* const* d_in, const int* in_sizes, int n_in,
                              void* d_out, int out_size)
{
    // Robust input mapping: pred has NN elements, target has 2*NN.
    int pred_idx = 0, tgt_idx = 1;
    if (n_in >= 2 && in_sizes[0] > in_sizes[1]) { pred_idx = 1; tgt_idx = 0; }
    const float* pred   = (const float*)d_in[pred_idx];
    const float* target = (const float*)d_in[tgt_idx];
    float* out = (float*)d_out;

    svm_all<<<GRID, T>>>(pred, target, out);
}

// round 16
// speedup vs baseline: 1.1618x; 1.1618x over previous
#include <cuda_runtime.h>
#include <cuda_fp16.h>

#define NN 8192
#define THREADS 512
#define NJ 16                       // j's per thread (8 half2 regs)
#define NH (NJ / 2)                 // 8
#define GRID 296                    // 148 SMs * 2 CTAs -> one wave
#define ROWS_MAX 28                 // ceil(8192/296)

// Deterministic per-block partials + completion ticket.
__device__ float g_rank[GRID];
__device__ float g_cnt[GRID];
__device__ float g_reg[GRID];
__device__ unsigned int g_ticket;   // zero-init; reset by last block

__global__ void __launch_bounds__(THREADS, 2)
svm_fused_kernel(const float* __restrict__ pred,
                 const float* __restrict__ target,
                 float* __restrict__ out)
{
    const int tid = threadIdx.x;
    const int bid = blockIdx.x;

    // ---- Register-resident j data, packed half2 (2 j's per register) ----
    // Thread owns 16 consecutive j's: jbase = tid*16.
    half2 t2[NH], p2[NH];
    {
        const int jbase = tid * NJ;
        const float4* tgt4 = (const float4*)target;   // (t0,e0,t1,e1) per float4
        const float4* prd4 = (const float4*)pred;
        #pragma unroll
        for (int k = 0; k < NH; k += 2) {
            // two float4 of target = 4 j's (times at .x,.z)
            const float4 a = tgt4[(jbase >> 1) + k];
            const float4 b = tgt4[(jbase >> 1) + k + 1];
            t2[k]     = __floats2half2_rn(a.x, a.z);
            t2[k + 1] = __floats2half2_rn(b.x, b.z);
            // one float4 of pred = 4 j's
            const float4 pq = prd4[(jbase >> 2) + (k >> 1)];
            p2[k]     = __floats2half2_rn(pq.x, pq.y);
            p2[k + 1] = __floats2half2_rn(pq.z, pq.w);
        }
    }

    // ---- This block's rows -> shared memory ----
    __shared__ float s_ti[ROWS_MAX];
    __shared__ float s_ei[ROWS_MAX];
    __shared__ float s_pi[ROWS_MAX];
    if (tid < ROWS_MAX) {
        const int i = bid + tid * GRID;
        const bool v = (i < NN);
        const int ii = v ? i : 0;
        s_ti[tid] = target[2 * ii];
        s_pi[tid] = pred[ii];
        s_ei[tid] = v ? target[2 * ii + 1] : -1.0f;   // -1 marks invalid
    }
    __syncthreads();

    const half2 zero2 = __floats2half2_rn(0.f, 0.f);
    half2 acc0 = zero2, acc1 = zero2, acc2 = zero2, acc3 = zero2;
    half2 cnt0 = zero2, cnt1 = zero2;       // exact: <= 112 per half
    float reg_acc = 0.f;

    for (int r = 0; r < ROWS_MAX; ++r) {
        const float ei = s_ei[r];
        if (ei < 0.f) continue;             // invalid row (uniform)
        const float ti = s_ti[r];
        const float pi = s_pi[r];

        if (tid == 0) {                     // regression term, fp32 exact
            float d = pi - ti;
            if (ei == 0.f) d = fmaxf(d, 0.f);
            reg_acc = fmaf(d, d, reg_acc);
        }

        if (ei != 0.f) {                    // block-uniform branch
            const half2 ti2 = __float2half2_rn(ti);
            const half2 c2  = __float2half2_rn(1.0f + pi);
            #pragma unroll
            for (int k = 0; k < NH; k += 4) {
                {
                    const half2 m = __hgt2(t2[k], ti2);
                    const half2 h = __hmax2(__hsub2(c2, p2[k]), zero2);
                    const half2 mh = __hmul2(m, h);
                    acc0 = __hfma2(mh, h, acc0);
                    cnt0 = __hadd2(cnt0, m);
                }
                {
                    const half2 m = __hgt2(t2[k + 1], ti2);
                    const half2 h = __hmax2(__hsub2(c2, p2[k + 1]), zero2);
                    const half2 mh = __hmul2(m, h);
                    acc1 = __hfma2(mh, h, acc1);
                    cnt1 = __hadd2(cnt1, m);
                }
                {
                    const half2 m = __hgt2(t2[k + 2], ti2);
                    const half2 h = __hmax2(__hsub2(c2, p2[k + 2]), zero2);
                    const half2 mh = __hmul2(m, h);
                    acc2 = __hfma2(mh, h, acc2);
                    cnt0 = __hadd2(cnt0, m);
                }
                {
                    const half2 m = __hgt2(t2[k + 3], ti2);
                    const half2 h = __hmax2(__hsub2(c2, p2[k + 3]), zero2);
                    const half2 mh = __hmul2(m, h);
                    acc3 = __hfma2(mh, h, acc3);
                    cnt1 = __hadd2(cnt1, m);
                }
            }
        }
    }

    // ---- Convert packed accumulators to fp32 ----
    const float rank_acc =
        (__low2float(acc0) + __high2float(acc0)) +
        (__low2float(acc1) + __high2float(acc1)) +
        (__low2float(acc2) + __high2float(acc2)) +
        (__low2float(acc3) + __high2float(acc3));
    const float cnt_acc =
        (__low2float(cnt0) + __high2float(cnt0)) +
        (__low2float(cnt1) + __high2float(cnt1));   // exact integers

    // ---- Block reduction (shared tree, deterministic) ----
    __shared__ float red_r[THREADS];
    __shared__ float red_c[THREADS];
    __shared__ float red_g[THREADS];
    red_r[tid] = rank_acc;
    red_c[tid] = cnt_acc;                   // block sum < 2^24: exact in fp32
    red_g[tid] = reg_acc;
    __syncthreads();
    #pragma unroll
    for (int s = THREADS / 2; s > 0; s >>= 1) {
        if (tid < s) {
            red_r[tid] += red_r[tid + s];
            red_c[tid] += red_c[tid + s];
            red_g[tid] += red_g[tid + s];
        }
        __syncthreads();
    }

    // ---- Publish partial, grab completion ticket ----
    __shared__ bool s_last;
    if (tid == 0) {
        g_rank[bid] = red_r[0];
        g_cnt[bid]  = red_c[0];
        g_reg[bid]  = red_g[0];
        __threadfence();
        const unsigned int old = atomicAdd(&g_ticket, 1u);
        s_last = (old == GRID - 1);
    }
    __syncthreads();

    // ---- Last block: deterministic final combine ----
    if (s_last) {
        __threadfence();
        __shared__ double sr[THREADS];
        __shared__ double sc[THREADS];
        __shared__ double sg[THREADS];
        double rank = 0.0, cnt = 0.0, reg = 0.0;
        if (tid < GRID) {                   // 296 < 512: one element each
            rank = (double)g_rank[tid];
            cnt  = (double)g_cnt[tid];
            reg  = (double)g_reg[tid];
        }
        sr[tid] = rank; sc[tid] = cnt; sg[tid] = reg;
        __syncthreads();
        #pragma unroll
        for (int s = THREADS / 2; s > 0; s >>= 1) {
            if (tid < s) {
                sr[tid] += sr[tid + s];
                sc[tid] += sc[tid + s];
                sg[tid] += sg[tid + s];
            }
            __syncthreads();
        }
        if (tid == 0) {
            double c = sc[0];
            if (c < 1.0) c = 1.0;
            const double R = 0.5;
            const double loss = R * (sr[0] / c) + (1.0 - R) * (sg[0] / (double)NN);
            out[0] = (float)loss;
            g_ticket = 0;                   // reset for next graph replay
        }
    }
}

extern "C" void kernel_launch(void* const* d_in, const int* in_sizes, int n_in,
                              void* d_out, int out_size)
{
    // Robust input mapping: pred has NN elements, target has 2*NN.
    int pred_idx = 0, tgt_idx = 1;
    if (n_in >= 2 && in_sizes[0] > in_sizes[1]) { pred_idx = 1; tgt_idx = 0; }
    const float* pred   = (const float*)d_in[pred_idx];
    const float* target = (const float*)d_in[tgt_idx];
    float* out = (float*)d_out;

    svm_fused_kernel<<<GRID, THREADS>>>(pred, target, out);
}

// round 17
// speedup vs baseline: 1.2641x; 1.0880x over previous
#include <cuda_runtime.h>

#define NN 8192
#define THREADS 256
#define NJ 32                      // j's per thread: 256*32 = 8192
#define GRID 444                   // measured-best config (R3)
#define ROWS_MAX 19                // ceil(8192/444)

// Deterministic per-block partials + completion ticket.
__device__ float g_rank[GRID];
__device__ float g_cnt[GRID];
__device__ float g_reg[GRID];
__device__ unsigned int g_ticket;  // zero-init; reset by last block each replay

// Branchless predicated pair op: exactly 5 instructions, no BSSY/BSYNC.
__device__ __forceinline__ void pair_op(float tj, float pj, float ti, float c,
                                        float& acc, float& cntf)
{
    asm("{\n\t"
        ".reg .pred p;\n\t"
        ".reg .f32 d;\n\t"
        "setp.gt.f32 p, %2, %3;\n\t"          // t_j > t_i
        "sub.f32 d, %4, %5;\n\t"              // d = (1+p_i) - p_j
        "max.f32 d, d, 0f00000000;\n\t"       // h = max(d, 0)
        "@p fma.rn.f32 %0, d, d, %0;\n\t"     // acc += h*h  (masked)
        "@p add.f32 %1, %1, 0f3F800000;\n\t"  // cnt += 1    (masked)
        "}"
        : "+f"(acc), "+f"(cntf)
        : "f"(tj), "f"(ti), "f"(c), "f"(pj));
}

__global__ void __launch_bounds__(THREADS)
svm_fused_kernel(const float* __restrict__ pred,
                 const float* __restrict__ target,
                 float* __restrict__ out)
{
    const int tid = threadIdx.x;
    const int bid = blockIdx.x;

    // Register-resident j data: loaded once (coalesced), reused for every row.
    float tj[NJ], pjn[NJ];
    #pragma unroll
    for (int k = 0; k < NJ; ++k) {
        const int j = tid + k * THREADS;
        tj[k]  = target[2 * j];        // time[j]
        pjn[k] = pred[j];              // p[j]
    }

    float r0 = 0.f, r1 = 0.f, r2 = 0.f, r3 = 0.f;
    float c0 = 0.f, c1 = 0.f, c2 = 0.f, c3 = 0.f;
    float reg_acc = 0.f;

    for (int i = bid; i < NN; i += GRID) {
        const float ti = target[2 * i];
        const float ei = target[2 * i + 1];
        const float pi = pred[i];

        if (tid == 0) {                // regression term, once per row
            float d = pi - ti;
            if (ei == 0.f) d = fmaxf(d, 0.f);
            reg_acc = fmaf(d, d, reg_acc);
        }

        if (ei != 0.f) {               // block-uniform branch
            const float c = 1.0f + pi;
            #pragma unroll
            for (int k = 0; k < NJ; k += 4) {
                pair_op(tj[k],     pjn[k],     ti, c, r0, c0);
                pair_op(tj[k + 1], pjn[k + 1], ti, c, r1, c1);
                pair_op(tj[k + 2], pjn[k + 2], ti, c, r2, c2);
                pair_op(tj[k + 3], pjn[k + 3], ti, c, r3, c3);
            }
        }
    }

    const float rank_acc = (r0 + r1) + (r2 + r3);
    const float cnt_acc  = (c0 + c1) + (c2 + c3);   // <= 608/thread: exact fp32

    // Block reduction (shared tree, deterministic).
    __shared__ float red_r[THREADS];
    __shared__ float red_c[THREADS];
    __shared__ float red_g[THREADS];
    red_r[tid] = rank_acc;
    red_c[tid] = cnt_acc;              // block sum < 2^24: exact in fp32
    red_g[tid] = reg_acc;
    __syncthreads();
    #pragma unroll
    for (int s = THREADS / 2; s > 0; s >>= 1) {
        if (tid < s) {
            red_r[tid] += red_r[tid + s];
            red_c[tid] += red_c[tid + s];
            red_g[tid] += red_g[tid + s];
        }
        __syncthreads();
    }

    // Publish partial, grab completion ticket.
    __shared__ bool s_last;
    if (tid == 0) {
        g_rank[bid] = red_r[0];
        g_cnt[bid]  = red_c[0];
        g_reg[bid]  = red_g[0];
        __threadfence();
        const unsigned int old = atomicAdd(&g_ticket, 1u);
        s_last = (old == GRID - 1);
    }
    __syncthreads();

    // Last block performs the deterministic final combine.
    if (s_last) {
        __threadfence();
        __shared__ double sr[THREADS];
        __shared__ double sc[THREADS];
        __shared__ double sg[THREADS];
        double rank = 0.0, cnt = 0.0, reg = 0.0;
        #pragma unroll
        for (int k = 0; k < 2; ++k) {            // covers 444 with 256 threads
            const int b = tid + k * THREADS;
            if (b < GRID) {
                rank += (double)g_rank[b];
                cnt  += (double)g_cnt[b];
                reg  += (double)g_reg[b];
            }
        }
        sr[tid] = rank; sc[tid] = cnt; sg[tid] = reg;
        __syncthreads();
        #pragma unroll
        for (int s = THREADS / 2; s > 0; s >>= 1) {
            if (tid < s) {
                sr[tid] += sr[tid + s];
                sc[tid] += sc[tid + s];
                sg[tid] += sg[tid + s];
            }
            __syncthreads();
        }
        if (tid == 0) {
            double c = sc[0];
            if (c < 1.0) c = 1.0;
            const double R = 0.5;
            const double loss = R * (sr[0] / c) + (1.0 - R) * (sg[0] / (double)NN);
            out[0] = (float)loss;
            g_ticket = 0;                        // reset for next graph replay
        }
    }
}

extern "C" void kernel_launch(void* const* d_in, const int* in_sizes, int n_in,
                              void* d_out, int out_size)
{
    // Robust input mapping: pred has NN elements, target has 2*NN.
    int pred_idx = 0, tgt_idx = 1;
    if (n_in >= 2 && in_sizes[0] > in_sizes[1]) { pred_idx = 1; tgt_idx = 0; }
    const float* pred   = (const float*)d_in[pred_idx];
    const float* target = (const float*)d_in[tgt_idx];
    float* out = (float*)d_out;

    svm_fused_kernel<<<GRID, THREADS>>>(pred, target, out);
}